// round 2
// baseline (speedup 1.0000x reference)
#include <cuda_runtime.h>
#include <cuda_bf16.h>
#include <cstdint>
#include <cstddef>

#define DINL __device__ __forceinline__

// Problem dims (static)
// B=8, S=2048, H=1024, side=32, width=5

// ---------------- device scratch (no allocation allowed) ----------------
__device__ float g_wkT[25 * 1024];   // packed (Wk o M): g_wkT[d][h] = Wk[h][nb2(h,d)]
__device__ float g_wvT[25 * 1024];
__device__ float g_wcT[81 * 1024];   // packed composite Wc = (Wl o M)(Wq o M)
__device__ float g_bc[1024];         // (Wl o M) @ bq
__device__ float g_partial[8 * 16 * 1024]; // partial colsums of x
__device__ float g_colsumv[8 * 1024];      // exact colsum of v per batch
__device__ __nv_bfloat16 g_q2b[(size_t)8 * 2048 * 1024];
__device__ __nv_bfloat16 g_kb[(size_t)8 * 2048 * 1024];
__device__ __nv_bfloat16 g_vb[(size_t)8 * 2048 * 1024];
__device__ __nv_bfloat16 g_d[(size_t)8 * 2048 * 2048]; // probs - 1/2048

// ---------------- K0: pack sparse weights ----------------
__global__ void pack_kernel(const float* __restrict__ Wq,
                            const float* __restrict__ bq,
                            const float* __restrict__ Wk,
                            const float* __restrict__ Wv,
                            const float* __restrict__ Wl) {
    int t = blockIdx.x * blockDim.x + threadIdx.x;
    if (t < 1024 * 81) {
        int i = t / 81;
        int d = t - i * 81;
        int dr = d / 9 - 4, dc = d % 9 - 4;
        int ri = i >> 5, ci = i & 31;
        int jr = (ri + dr) & 31, jc = (ci + dc) & 31;
        int j = jr * 32 + jc;
        int erlo = dr - 2 < -2 ? -2 : dr - 2;
        int erhi = dr + 2 > 2 ? 2 : dr + 2;
        int eclo = dc - 2 < -2 ? -2 : dc - 2;
        int echi = dc + 2 > 2 ? 2 : dc + 2;
        float s = 0.f;
        for (int er = erlo; er <= erhi; ++er) {
            int mr = ((ri + er) & 31) * 32;
            for (int ec = eclo; ec <= echi; ++ec) {
                int m = mr + ((ci + ec) & 31);
                s += Wl[i * 1024 + m] * Wq[m * 1024 + j];
            }
        }
        g_wcT[d * 1024 + i] = s;
    }
    if (t < 1024) {
        int i = t;
        int ri = i >> 5, ci = i & 31;
        float b = 0.f;
        for (int d = 0; d < 25; ++d) {
            int dr = d / 5 - 2, dc = d % 5 - 2;
            int m = ((ri + dr) & 31) * 32 + ((ci + dc) & 31);
            g_wkT[d * 1024 + i] = Wk[i * 1024 + m];
            g_wvT[d * 1024 + i] = Wv[i * 1024 + m];
            b += Wl[i * 1024 + m] * bq[m];
        }
        g_bc[i] = b;
    }
}

// ---------------- K0b: partial column sums of x ----------------
__global__ __launch_bounds__(256) void colsumx_kernel(const float* __restrict__ x) {
    int b = blockIdx.y, ch = blockIdx.x; // 8 x 16
    const float4* xr = (const float4*)x + ((size_t)b * 2048 + ch * 128) * 256;
    float4 acc = make_float4(0.f, 0.f, 0.f, 0.f);
    for (int s = 0; s < 128; ++s) {
        float4 v = xr[(size_t)s * 256 + threadIdx.x];
        acc.x += v.x; acc.y += v.y; acc.z += v.z; acc.w += v.w;
    }
    ((float4*)g_partial)[(b * 16 + ch) * 256 + threadIdx.x] = acc;
}

// ---------------- K0c: exact colsum(v) via sparse projection ----------------
__global__ __launch_bounds__(256) void colsumv_kernel(const float* __restrict__ bv) {
    int b = blockIdx.x;
    __shared__ float sx[1024];
    float4 acc = make_float4(0.f, 0.f, 0.f, 0.f);
    for (int ch = 0; ch < 16; ++ch) {
        float4 v = ((float4*)g_partial)[(b * 16 + ch) * 256 + threadIdx.x];
        acc.x += v.x; acc.y += v.y; acc.z += v.z; acc.w += v.w;
    }
    ((float4*)sx)[threadIdx.x] = acc;
    __syncthreads();
    for (int h = threadIdx.x; h < 1024; h += 256) {
        int ri = h >> 5, ci = h & 31;
        float s = 0.f;
#pragma unroll
        for (int d = 0; d < 25; ++d) {
            int dr = d / 5 - 2, dc = d % 5 - 2;
            s += g_wvT[d * 1024 + h] * sx[((ri + dr) & 31) * 32 + ((ci + dc) & 31)];
        }
        g_colsumv[b * 1024 + h] = s + 2048.f * bv[h];
    }
}

// ---------------- K1: fused sparse projections (q2, k, v) ----------------
__global__ __launch_bounds__(256) void proj_kernel(const float* __restrict__ x,
                                                   const float* __restrict__ bk,
                                                   const float* __restrict__ bv) {
    __shared__ float xs[8][1024];
    const int rowBase = blockIdx.x * 8; // global row in [0, 16384)
    {
        const float4* xg = (const float4*)x + (size_t)rowBase * 256;
        float4* xs4 = (float4*)xs;
        for (int i = threadIdx.x; i < 8 * 256; i += 256) xs4[i] = xg[i];
    }
    __syncthreads();
    const size_t outBase = (size_t)rowBase * 1024;

    for (int it = 0; it < 2; ++it) {
        int p = threadIdx.x + it * 256; // pair index 0..511
        int h0 = p * 2, h1 = h0 + 1;
        int r0 = h0 >> 5, c0 = h0 & 31; // c0 even
        float aq0[8], aq1[8], ak0[8], ak1[8], av0[8], av1[8];
#pragma unroll
        for (int r = 0; r < 8; ++r) { aq0[r]=0.f; aq1[r]=0.f; ak0[r]=0.f; ak1[r]=0.f; av0[r]=0.f; av1[r]=0.f; }

        for (int dr = -4; dr <= 4; ++dr) {
            int rowOff = ((r0 + dr) & 31) * 32;
            bool kvr = (dr >= -2 && dr <= 2);
#pragma unroll
            for (int dce = 0; dce < 5; ++dce) {
                int dca = 2 * dce - 4; // -4,-2,0,2,4 (even)
                int col = (c0 + dca) & 31;
                int dbase = (dr + 4) * 9 + (dca + 4);
                float wql0 = g_wcT[dbase * 1024 + h0];
                float wqh0 = (dce < 4) ? g_wcT[(dbase + 1) * 1024 + h0] : 0.f;
                float wql1 = (dce > 0) ? g_wcT[(dbase - 1) * 1024 + h1] : 0.f;
                float wqh1 = g_wcT[dbase * 1024 + h1];

                bool kvAct = kvr && (dce >= 1) && (dce <= 3);
                if (kvAct) {
                    int kb0 = (dr + 2) * 5 + (dca + 2);
                    float wkl0 = g_wkT[kb0 * 1024 + h0];
                    float wvl0 = g_wvT[kb0 * 1024 + h0];
                    float wkh1 = g_wkT[kb0 * 1024 + h1];
                    float wvh1 = g_wvT[kb0 * 1024 + h1];
                    float wkh0 = 0.f, wvh0 = 0.f, wkl1 = 0.f, wvl1 = 0.f;
                    if (dce <= 2) { wkh0 = g_wkT[(kb0 + 1) * 1024 + h0]; wvh0 = g_wvT[(kb0 + 1) * 1024 + h0]; }
                    if (dce >= 2) { wkl1 = g_wkT[(kb0 - 1) * 1024 + h1]; wvl1 = g_wvT[(kb0 - 1) * 1024 + h1]; }
#pragma unroll
                    for (int r = 0; r < 8; ++r) {
                        float2 xv = *(const float2*)&xs[r][rowOff + col];
                        aq0[r] += wql0 * xv.x + wqh0 * xv.y;
                        aq1[r] += wql1 * xv.x + wqh1 * xv.y;
                        ak0[r] += wkl0 * xv.x + wkh0 * xv.y;
                        ak1[r] += wkl1 * xv.x + wkh1 * xv.y;
                        av0[r] += wvl0 * xv.x + wvh0 * xv.y;
                        av1[r] += wvl1 * xv.x + wvh1 * xv.y;
                    }
                } else {
#pragma unroll
                    for (int r = 0; r < 8; ++r) {
                        float2 xv = *(const float2*)&xs[r][rowOff + col];
                        aq0[r] += wql0 * xv.x + wqh0 * xv.y;
                        aq1[r] += wql1 * xv.x + wqh1 * xv.y;
                    }
                }
            }
        }
        float bc0 = g_bc[h0], bc1 = g_bc[h1];
        float bk0 = bk[h0], bk1 = bk[h1];
        float bv0 = bv[h0], bv1 = bv[h1];
#pragma unroll
        for (int r = 0; r < 8; ++r) {
            size_t ob = outBase + (size_t)r * 1024 + h0;
            __nv_bfloat162 q2; q2.x = __float2bfloat16(aq0[r] + bc0); q2.y = __float2bfloat16(aq1[r] + bc1);
            __nv_bfloat162 kk; kk.x = __float2bfloat16(ak0[r] + bk0); kk.y = __float2bfloat16(ak1[r] + bk1);
            __nv_bfloat162 vv; vv.x = __float2bfloat16(av0[r] + bv0); vv.y = __float2bfloat16(av1[r] + bv1);
            *(__nv_bfloat162*)&g_q2b[ob] = q2;
            *(__nv_bfloat162*)&g_kb[ob] = kk;
            *(__nv_bfloat162*)&g_vb[ob] = vv;
        }
    }
}

// ---------------- GEMM (mma.sync bf16, fp32 accum) ----------------
DINL void ldsm4(uint32_t* r, uint32_t addr) {
    asm volatile("ldmatrix.sync.aligned.m8n8.x4.shared.b16 {%0,%1,%2,%3}, [%4];"
                 : "=r"(r[0]), "=r"(r[1]), "=r"(r[2]), "=r"(r[3]) : "r"(addr));
}
DINL void ldsm4t(uint32_t* r, uint32_t addr) {
    asm volatile("ldmatrix.sync.aligned.m8n8.x4.trans.shared.b16 {%0,%1,%2,%3}, [%4];"
                 : "=r"(r[0]), "=r"(r[1]), "=r"(r[2]), "=r"(r[3]) : "r"(addr));
}
DINL void mma16816(float* c, const uint32_t* a, const uint32_t* b) {
    asm volatile(
        "mma.sync.aligned.m16n8k16.row.col.f32.bf16.bf16.f32 "
        "{%0,%1,%2,%3},{%4,%5,%6,%7},{%8,%9},{%0,%1,%2,%3};\n"
        : "+f"(c[0]), "+f"(c[1]), "+f"(c[2]), "+f"(c[3])
        : "r"(a[0]), "r"(a[1]), "r"(a[2]), "r"(a[3]), "r"(b[0]), "r"(b[1]));
}
DINL void cpasync16(uint32_t dst, const void* src) {
    asm volatile("cp.async.cg.shared.global [%0], [%1], 16;" :: "r"(dst), "l"(src));
}

// MODE 0: QK  — B is [N][K] k-major (k-tensor), C = scores, scale 1/32
// MODE 1: PV  — B is [K][N] n-major (v-tensor), C = out, + colsumv/2048 bias
template <int MODE>
__global__ __launch_bounds__(256) void gemm_kernel(
    const __nv_bfloat16* __restrict__ A, const __nv_bfloat16* __restrict__ Bm,
    float* __restrict__ C, const float* __restrict__ bias,
    int K, int lda, int ldb, int ldc,
    size_t strideA, size_t strideB, size_t strideC, float scale) {
    constexpr int SAS = 40;
    constexpr int SBS = (MODE == 0) ? 40 : 136;
    constexpr int BROW = (MODE == 0) ? 128 : 32;
    __shared__ __align__(16) __nv_bfloat16 sA[2][128 * SAS];
    __shared__ __align__(16) __nv_bfloat16 sB[2][BROW * SBS];

    const int bz = blockIdx.z;
    const int m0 = blockIdx.y * 128, n0 = blockIdx.x * 128;
    const __nv_bfloat16* Ab = A + strideA * bz;
    const __nv_bfloat16* Bb = Bm + strideB * bz;
    float* Cb = C + strideC * bz;
    const int tid = threadIdx.x, lane = tid & 31, warp = tid >> 5;
    const int wm = (warp >> 2) * 64, wn = (warp & 3) * 32;

    const int ar = tid >> 2, ac = (tid & 3) * 8;
    const int br = (MODE == 0) ? (tid >> 2) : (tid >> 4);
    const int bcol = (MODE == 0) ? (tid & 3) * 8 : (tid & 15) * 8;

    float c[4][4][4];
#pragma unroll
    for (int i = 0; i < 4; ++i)
#pragma unroll
        for (int j = 0; j < 4; ++j)
#pragma unroll
            for (int q = 0; q < 4; ++q) c[i][j][q] = 0.f;

    auto loadTile = [&](int kt, int buf) {
        int k0 = kt * 32;
        {
            const __nv_bfloat16* g = Ab + (size_t)(m0 + ar) * lda + k0 + ac;
            uint32_t d = (uint32_t)__cvta_generic_to_shared(&sA[buf][ar * SAS + ac]);
            cpasync16(d, g);
            cpasync16(d + 64 * SAS * 2, g + (size_t)64 * lda);
        }
        if (MODE == 0) {
            const __nv_bfloat16* g = Bb + (size_t)(n0 + br) * ldb + k0 + bcol;
            uint32_t d = (uint32_t)__cvta_generic_to_shared(&sB[buf][br * SBS + bcol]);
            cpasync16(d, g);
            cpasync16(d + 64 * SBS * 2, g + (size_t)64 * ldb);
        } else {
            const __nv_bfloat16* g = Bb + (size_t)(k0 + br) * ldb + n0 + bcol;
            uint32_t d = (uint32_t)__cvta_generic_to_shared(&sB[buf][br * SBS + bcol]);
            cpasync16(d, g);
            cpasync16(d + 16 * SBS * 2, g + (size_t)16 * ldb);
        }
    };

    loadTile(0, 0);
    asm volatile("cp.async.commit_group;");
    const int KT = K >> 5;
    for (int kt = 0; kt < KT; ++kt) {
        if (kt + 1 < KT) {
            loadTile(kt + 1, (kt + 1) & 1);
            asm volatile("cp.async.commit_group;");
            asm volatile("cp.async.wait_group 1;");
        } else {
            asm volatile("cp.async.wait_group 0;");
        }
        __syncthreads();
        const __nv_bfloat16* cA = sA[kt & 1];
        const __nv_bfloat16* cB = sB[kt & 1];
#pragma unroll
        for (int ks = 0; ks < 32; ks += 16) {
            uint32_t af[4][4];
#pragma unroll
            for (int mi = 0; mi < 4; ++mi) {
                uint32_t addr = (uint32_t)__cvta_generic_to_shared(
                    &cA[(wm + mi * 16 + (lane & 15)) * SAS + ks + ((lane >> 4) << 3)]);
                ldsm4(af[mi], addr);
            }
            uint32_t bf[4][2];
#pragma unroll
            for (int nj = 0; nj < 2; ++nj) {
                uint32_t r[4];
                if (MODE == 0) {
                    int rowb = wn + nj * 16 + (lane & 7) + (((lane >> 4) & 1) << 3);
                    int kof = ks + (((lane >> 3) & 1) << 3);
                    uint32_t addr = (uint32_t)__cvta_generic_to_shared(&cB[rowb * SBS + kof]);
                    ldsm4(r, addr);
                } else {
                    int krow = ks + (lane & 7) + (((lane >> 3) & 1) << 3);
                    int ncol = wn + nj * 16 + ((lane >> 4) << 3);
                    uint32_t addr = (uint32_t)__cvta_generic_to_shared(&cB[krow * SBS + ncol]);
                    ldsm4t(r, addr);
                }
                bf[nj * 2][0] = r[0]; bf[nj * 2][1] = r[1];
                bf[nj * 2 + 1][0] = r[2]; bf[nj * 2 + 1][1] = r[3];
            }
#pragma unroll
            for (int mi = 0; mi < 4; ++mi)
#pragma unroll
                for (int ni = 0; ni < 4; ++ni) mma16816(c[mi][ni], af[mi], bf[ni]);
        }
        __syncthreads();
    }

    // epilogue
#pragma unroll
    for (int mi = 0; mi < 4; ++mi) {
        int r0 = m0 + wm + mi * 16 + (lane >> 2);
#pragma unroll
        for (int ni = 0; ni < 4; ++ni) {
            int col = n0 + wn + ni * 8 + (lane & 3) * 2;
            float bx = 0.f, by = 0.f;
            if (MODE == 1) {
                bx = bias[bz * 1024 + col] * (1.f / 2048.f);
                by = bias[bz * 1024 + col + 1] * (1.f / 2048.f);
            }
            float2 o0 = make_float2(c[mi][ni][0] * scale + bx, c[mi][ni][1] * scale + by);
            float2 o1 = make_float2(c[mi][ni][2] * scale + bx, c[mi][ni][3] * scale + by);
            *(float2*)&Cb[(size_t)r0 * ldc + col] = o0;
            *(float2*)&Cb[(size_t)(r0 + 8) * ldc + col] = o1;
        }
    }
}

// ---------------- softmax (in-place on probs region) + residual d ----------------
__global__ __launch_bounds__(256) void softmax_kernel(float* __restrict__ probs) {
    const size_t row = blockIdx.x; // 0..16383
    float* pr = probs + row * 2048;
    __nv_bfloat16* dd = g_d + row * 2048;
    const int tid = threadIdx.x;
    float4 v0 = ((const float4*)pr)[tid];
    float4 v1 = ((const float4*)pr)[tid + 256];
    float m = fmaxf(fmaxf(fmaxf(v0.x, v0.y), fmaxf(v0.z, v0.w)),
                    fmaxf(fmaxf(v1.x, v1.y), fmaxf(v1.z, v1.w)));
    __shared__ float redm[8];
    __shared__ float reds[8];
#pragma unroll
    for (int off = 16; off; off >>= 1) m = fmaxf(m, __shfl_xor_sync(0xffffffffu, m, off));
    if ((tid & 31) == 0) redm[tid >> 5] = m;
    __syncthreads();
    m = redm[0];
#pragma unroll
    for (int i = 1; i < 8; ++i) m = fmaxf(m, redm[i]);

    float e[8];
    e[0] = __expf(v0.x - m); e[1] = __expf(v0.y - m); e[2] = __expf(v0.z - m); e[3] = __expf(v0.w - m);
    e[4] = __expf(v1.x - m); e[5] = __expf(v1.y - m); e[6] = __expf(v1.z - m); e[7] = __expf(v1.w - m);
    float s = 0.f;
#pragma unroll
    for (int i = 0; i < 8; ++i) s += e[i];
#pragma unroll
    for (int off = 16; off; off >>= 1) s += __shfl_xor_sync(0xffffffffu, s, off);
    __syncthreads(); // protect redm reads above before reusing shared
    if ((tid & 31) == 0) reds[tid >> 5] = s;
    __syncthreads();
    s = 0.f;
#pragma unroll
    for (int i = 0; i < 8; ++i) s += reds[i];
    float inv = 1.f / s;
    const float cmean = 0.00048828125f; // 1/2048 exact

    float p0 = e[0] * inv, p1 = e[1] * inv, p2 = e[2] * inv, p3 = e[3] * inv;
    float p4 = e[4] * inv, p5 = e[5] * inv, p6 = e[6] * inv, p7 = e[7] * inv;
    ((float4*)pr)[tid] = make_float4(p0, p1, p2, p3);
    ((float4*)pr)[tid + 256] = make_float4(p4, p5, p6, p7);
    __nv_bfloat162 d01, d23, d45, d67;
    d01.x = __float2bfloat16(p0 - cmean); d01.y = __float2bfloat16(p1 - cmean);
    d23.x = __float2bfloat16(p2 - cmean); d23.y = __float2bfloat16(p3 - cmean);
    d45.x = __float2bfloat16(p4 - cmean); d45.y = __float2bfloat16(p5 - cmean);
    d67.x = __float2bfloat16(p6 - cmean); d67.y = __float2bfloat16(p7 - cmean);
    *(__nv_bfloat162*)&dd[tid * 4] = d01;
    *(__nv_bfloat162*)&dd[tid * 4 + 2] = d23;
    *(__nv_bfloat162*)&dd[(tid + 256) * 4] = d45;
    *(__nv_bfloat162*)&dd[(tid + 256) * 4 + 2] = d67;
}

// ---------------- launch ----------------
extern "C" void kernel_launch(void* const* d_in, const int* in_sizes, int n_in,
                              void* d_out, int out_size) {
    const float* x  = (const float*)d_in[0];
    const float* Wq = (const float*)d_in[1];
    const float* bq = (const float*)d_in[2];
    const float* Wk = (const float*)d_in[3];
    const float* bk = (const float*)d_in[4];
    const float* Wv = (const float*)d_in[5];
    const float* bv = (const float*)d_in[6];
    const float* Wl = (const float*)d_in[7];

    float* out = (float*)d_out;                        // [8,2048,1024]
    float* probs = out + (size_t)8 * 2048 * 1024;      // [8,2048,2048]

    __nv_bfloat16 *q2b, *kb, *vb, *dres;
    float *colsumv;
    cudaGetSymbolAddress((void**)&q2b, g_q2b);
    cudaGetSymbolAddress((void**)&kb, g_kb);
    cudaGetSymbolAddress((void**)&vb, g_vb);
    cudaGetSymbolAddress((void**)&dres, g_d);
    cudaGetSymbolAddress((void**)&colsumv, g_colsumv);

    pack_kernel<<<(1024 * 81 + 255) / 256, 256>>>(Wq, bq, Wk, Wv, Wl);
    colsumx_kernel<<<dim3(16, 8), 256>>>(x);
    colsumv_kernel<<<8, 256>>>(bv);
    proj_kernel<<<2048, 256>>>(x, bk, bv);

    // scores -> probs region of d_out
    gemm_kernel<0><<<dim3(16, 16, 8), 256>>>(
        q2b, kb, probs, nullptr,
        1024, 1024, 1024, 2048,
        (size_t)2048 * 1024, (size_t)2048 * 1024, (size_t)2048 * 2048, 0.03125f);

    softmax_kernel<<<16384, 256>>>(probs);

    // out = d @ v + colsumv/2048
    gemm_kernel<1><<<dim3(8, 16, 8), 256>>>(
        dres, vb, out, colsumv,
        2048, 2048, 1024, 1024,
        (size_t)2048 * 2048, (size_t)2048 * 1024, (size_t)2048 * 1024, 1.0f);
}

// round 3
// speedup vs baseline: 1.1000x; 1.1000x over previous
#include <cuda_runtime.h>
#include <cuda_bf16.h>
#include <cstdint>
#include <cstddef>

#define DINL __device__ __forceinline__

// B=8, S=2048, H=1024, side=32, q-window 9x9 (composite), kv-window 5x5

// ---------------- device scratch ----------------
__device__ float g_wvT[25 * 1024];         // fp32 packed (Wv o M) for exact colsumv
__device__ float g_bc[1024];               // (Wl o M) @ bq
__device__ float g_partial[8 * 16 * 1024];
__device__ float g_colsumv[8 * 1024];
__device__ __nv_bfloat16 g_wB[32 * 9 * 96 * 32];  // [rj][dr][n(q32|k32|v32)][k]
__device__ __nv_bfloat16 g_xb[(size_t)8 * 2048 * 1024];
__device__ __nv_bfloat16 g_q2b[(size_t)8 * 2048 * 1024];
__device__ __nv_bfloat16 g_kb[(size_t)8 * 2048 * 1024];
__device__ __nv_bfloat16 g_vb[(size_t)8 * 2048 * 1024];

DINL int circd(int a, int b) { int d = a - b; if (d < 0) d = -d; return d > 16 ? 32 - d : d; }

// ---------------- K0: pack weights ----------------
__global__ void pack_kernel(const float* __restrict__ Wq,
                            const float* __restrict__ bq,
                            const float* __restrict__ Wk,
                            const float* __restrict__ Wv,
                            const float* __restrict__ Wl) {
    int t = blockIdx.x * blockDim.x + threadIdx.x;
    if (t < 32 * 9 * 96 * 32) {
        int rj = t / 27648;
        int rem = t - rj * 27648;
        int dr = rem / 3072;
        int rem2 = rem - dr * 3072;
        int n = rem2 >> 5, k = rem2 & 31;
        int rd = dr - 4;
        int jr = (rj + rd) & 31;
        int j = jr * 32 + k;
        float val = 0.f;
        if (n < 32) {
            int i = rj * 32 + n;
            for (int er = -2; er <= 2; ++er) {
                int mr = (rj + er) & 31;
                if (circd(mr, jr) > 2) continue;
                for (int ec = -2; ec <= 2; ++ec) {
                    int mc = (n + ec) & 31;
                    if (circd(mc, k) > 2) continue;
                    int m = mr * 32 + mc;
                    val += Wl[i * 1024 + m] * Wq[m * 1024 + j];
                }
            }
        } else {
            int c_out = n & 31;
            int ard = rd < 0 ? -rd : rd;
            if (ard <= 2 && circd(c_out, k) <= 2) {
                int i = rj * 32 + c_out;
                val = (n < 64 ? Wk : Wv)[i * 1024 + j];
            }
        }
        g_wB[t] = __float2bfloat16(val);
    }
    if (t < 1024) {
        int i = t;
        int ri = i >> 5, ci = i & 31;
        float b = 0.f;
        for (int d = 0; d < 25; ++d) {
            int dr = d / 5 - 2, dc = d % 5 - 2;
            int m = ((ri + dr) & 31) * 32 + ((ci + dc) & 31);
            g_wvT[d * 1024 + i] = Wv[i * 1024 + m];
            b += Wl[i * 1024 + m] * bq[m];
        }
        g_bc[i] = b;
    }
}

// ---------------- K0b/K0c: exact colsum(v) ----------------
__global__ __launch_bounds__(256) void colsumx_kernel(const float* __restrict__ x) {
    int b = blockIdx.y, ch = blockIdx.x;
    const float4* xr = (const float4*)x + ((size_t)b * 2048 + ch * 128) * 256;
    float4 acc = make_float4(0.f, 0.f, 0.f, 0.f);
    for (int s = 0; s < 128; ++s) {
        float4 v = xr[(size_t)s * 256 + threadIdx.x];
        acc.x += v.x; acc.y += v.y; acc.z += v.z; acc.w += v.w;
    }
    ((float4*)g_partial)[(b * 16 + ch) * 256 + threadIdx.x] = acc;
}

__global__ __launch_bounds__(256) void colsumv_kernel(const float* __restrict__ bv) {
    int b = blockIdx.x;
    __shared__ float sx[1024];
    float4 acc = make_float4(0.f, 0.f, 0.f, 0.f);
    for (int ch = 0; ch < 16; ++ch) {
        float4 v = ((float4*)g_partial)[(b * 16 + ch) * 256 + threadIdx.x];
        acc.x += v.x; acc.y += v.y; acc.z += v.z; acc.w += v.w;
    }
    ((float4*)sx)[threadIdx.x] = acc;
    __syncthreads();
    for (int h = threadIdx.x; h < 1024; h += 256) {
        int ri = h >> 5, ci = h & 31;
        float s = 0.f;
#pragma unroll
        for (int d = 0; d < 25; ++d) {
            int dr = d / 5 - 2, dc = d % 5 - 2;
            s += g_wvT[d * 1024 + h] * sx[((ri + dr) & 31) * 32 + ((ci + dc) & 31)];
        }
        g_colsumv[b * 1024 + h] = s + 2048.f * bv[h];
    }
}

// ---------------- K1a: x -> bf16 ----------------
__global__ __launch_bounds__(256) void convert_kernel(const float* __restrict__ x) {
    size_t t = (size_t)blockIdx.x * 256 + threadIdx.x; // 2,097,152 threads x 8 elems
    const float4* x4 = (const float4*)x;
    float4 a = x4[2 * t], b = x4[2 * t + 1];
    __nv_bfloat162 p0 = __floats2bfloat162_rn(a.x, a.y);
    __nv_bfloat162 p1 = __floats2bfloat162_rn(a.z, a.w);
    __nv_bfloat162 p2 = __floats2bfloat162_rn(b.x, b.y);
    __nv_bfloat162 p3 = __floats2bfloat162_rn(b.z, b.w);
    uint4 o;
    o.x = *(uint32_t*)&p0; o.y = *(uint32_t*)&p1; o.z = *(uint32_t*)&p2; o.w = *(uint32_t*)&p3;
    ((uint4*)g_xb)[t] = o;
}

// ---------------- mma helpers ----------------
DINL void ldsm4(uint32_t* r, uint32_t addr) {
    asm volatile("ldmatrix.sync.aligned.m8n8.x4.shared.b16 {%0,%1,%2,%3}, [%4];"
                 : "=r"(r[0]), "=r"(r[1]), "=r"(r[2]), "=r"(r[3]) : "r"(addr));
}
DINL void ldsm4t(uint32_t* r, uint32_t addr) {
    asm volatile("ldmatrix.sync.aligned.m8n8.x4.trans.shared.b16 {%0,%1,%2,%3}, [%4];"
                 : "=r"(r[0]), "=r"(r[1]), "=r"(r[2]), "=r"(r[3]) : "r"(addr));
}
DINL void mma16816(float* c, const uint32_t* a, const uint32_t* b) {
    asm volatile(
        "mma.sync.aligned.m16n8k16.row.col.f32.bf16.bf16.f32 "
        "{%0,%1,%2,%3},{%4,%5,%6,%7},{%8,%9},{%0,%1,%2,%3};\n"
        : "+f"(c[0]), "+f"(c[1]), "+f"(c[2]), "+f"(c[3])
        : "r"(a[0]), "r"(a[1]), "r"(a[2]), "r"(a[3]), "r"(b[0]), "r"(b[1]));
}
DINL void cpasync16(uint32_t dst, const void* src) {
    asm volatile("cp.async.cg.shared.global [%0], [%1], 16;" :: "r"(dst), "l"(src));
}

// ---------------- K1b: block-banded projection GEMM (q2|k|v) ----------------
__global__ __launch_bounds__(256) void projmma_kernel(const float* __restrict__ bk,
                                                      const float* __restrict__ bv) {
    const int rj = blockIdx.x;           // 32 output block-cols
    const int m0 = blockIdx.y * 128;     // 128 row tiles
    __shared__ __align__(16) __nv_bfloat16 sX[2][128 * 40];
    __shared__ __align__(16) __nv_bfloat16 sW[2][96 * 40];
    const __nv_bfloat16* Wg = g_wB + (size_t)rj * 27648;
    const int tid = threadIdx.x, lane = tid & 31, warp = tid >> 5;
    const int wm = (warp >> 1) * 32, wn = (warp & 1) * 48;

    float c[2][6][4];
#pragma unroll
    for (int i = 0; i < 2; ++i)
#pragma unroll
        for (int j = 0; j < 6; ++j)
#pragma unroll
            for (int q = 0; q < 4; ++q) c[i][j][q] = 0.f;

    auto loadStage = [&](int dr, int buf) {
        int src_rb = (rj + dr - 4) & 31;
        const __nv_bfloat16* xg = g_xb + (size_t)m0 * 1024 + src_rb * 32;
#pragma unroll
        for (int i = 0; i < 2; ++i) {
            int idx = tid + 256 * i;
            int r = idx >> 2, ch = idx & 3;
            cpasync16((uint32_t)__cvta_generic_to_shared(&sX[buf][r * 40 + ch * 8]),
                      xg + (size_t)r * 1024 + ch * 8);
        }
        {
            int r = tid >> 2, ch = tid & 3;
            cpasync16((uint32_t)__cvta_generic_to_shared(&sW[buf][r * 40 + ch * 8]),
                      Wg + dr * 3072 + r * 32 + ch * 8);
            int idx = tid + 256;
            if (idx < 384) {
                r = idx >> 2; ch = idx & 3;
                cpasync16((uint32_t)__cvta_generic_to_shared(&sW[buf][r * 40 + ch * 8]),
                          Wg + dr * 3072 + r * 32 + ch * 8);
            }
        }
    };

    loadStage(0, 0);
    asm volatile("cp.async.commit_group;");
    for (int dr = 0; dr < 9; ++dr) {
        if (dr < 8) {
            loadStage(dr + 1, (dr + 1) & 1);
            asm volatile("cp.async.commit_group;");
            asm volatile("cp.async.wait_group 1;");
        } else {
            asm volatile("cp.async.wait_group 0;");
        }
        __syncthreads();
        const __nv_bfloat16* cX = sX[dr & 1];
        const __nv_bfloat16* cW = sW[dr & 1];
#pragma unroll
        for (int ks = 0; ks < 32; ks += 16) {
            uint32_t af[2][4];
#pragma unroll
            for (int mi = 0; mi < 2; ++mi) {
                uint32_t addr = (uint32_t)__cvta_generic_to_shared(
                    &cX[(wm + mi * 16 + (lane & 15)) * 40 + ks + ((lane >> 4) << 3)]);
                ldsm4(af[mi], addr);
            }
            uint32_t bf[6][2];
#pragma unroll
            for (int bj = 0; bj < 3; ++bj) {
                uint32_t r[4];
                int rowb = wn + bj * 16 + (lane & 7) + (((lane >> 4) & 1) << 3);
                int kof = ks + (((lane >> 3) & 1) << 3);
                uint32_t addr = (uint32_t)__cvta_generic_to_shared(&cW[rowb * 40 + kof]);
                ldsm4(r, addr);
                bf[bj * 2][0] = r[0]; bf[bj * 2][1] = r[1];
                bf[bj * 2 + 1][0] = r[2]; bf[bj * 2 + 1][1] = r[3];
            }
#pragma unroll
            for (int mi = 0; mi < 2; ++mi)
#pragma unroll
                for (int ni = 0; ni < 6; ++ni) mma16816(c[mi][ni], af[mi], bf[ni]);
        }
        __syncthreads();
    }

    // epilogue: route q|k|v columns
#pragma unroll
    for (int mi = 0; mi < 2; ++mi) {
        int r0 = m0 + wm + mi * 16 + (lane >> 2);
#pragma unroll
        for (int ni = 0; ni < 6; ++ni) {
            int nf = wn + ni * 8 + (lane & 3) * 2;
            __nv_bfloat16* dst;
            float b0, b1;
            int h;
            if (nf < 32) { dst = g_q2b; h = rj * 32 + nf; b0 = g_bc[h]; b1 = g_bc[h + 1]; }
            else if (nf < 64) { dst = g_kb; h = rj * 32 + nf - 32; b0 = bk[h]; b1 = bk[h + 1]; }
            else { dst = g_vb; h = rj * 32 + nf - 64; b0 = bv[h]; b1 = bv[h + 1]; }
            __nv_bfloat162 o0 = __floats2bfloat162_rn(c[mi][ni][0] + b0, c[mi][ni][1] + b1);
            __nv_bfloat162 o1 = __floats2bfloat162_rn(c[mi][ni][2] + b0, c[mi][ni][3] + b1);
            *(__nv_bfloat162*)&dst[(size_t)r0 * 1024 + h] = o0;
            *(__nv_bfloat162*)&dst[(size_t)(r0 + 8) * 1024 + h] = o1;
        }
    }
}

// ---------------- K2: QK GEMM (scores -> probs region) ----------------
__global__ __launch_bounds__(256) void qk_kernel(
    const __nv_bfloat16* __restrict__ A, const __nv_bfloat16* __restrict__ Bm,
    float* __restrict__ C) {
    constexpr int SAS = 40, SBS = 40;
    __shared__ __align__(16) __nv_bfloat16 sA[2][128 * SAS];
    __shared__ __align__(16) __nv_bfloat16 sB[2][128 * SBS];
    const int bz = blockIdx.z;
    const int m0 = blockIdx.y * 128, n0 = blockIdx.x * 128;
    const __nv_bfloat16* Ab = A + (size_t)bz * 2048 * 1024;
    const __nv_bfloat16* Bb = Bm + (size_t)bz * 2048 * 1024;
    float* Cb = C + (size_t)bz * 2048 * 2048;
    const int tid = threadIdx.x, lane = tid & 31, warp = tid >> 5;
    const int wm = (warp >> 2) * 64, wn = (warp & 3) * 32;
    const int ar = tid >> 2, ac = (tid & 3) * 8;

    float c[4][4][4];
#pragma unroll
    for (int i = 0; i < 4; ++i)
#pragma unroll
        for (int j = 0; j < 4; ++j)
#pragma unroll
            for (int q = 0; q < 4; ++q) c[i][j][q] = 0.f;

    auto loadTile = [&](int kt, int buf) {
        int k0 = kt * 32;
        const __nv_bfloat16* g = Ab + (size_t)(m0 + ar) * 1024 + k0 + ac;
        uint32_t d = (uint32_t)__cvta_generic_to_shared(&sA[buf][ar * SAS + ac]);
        cpasync16(d, g);
        cpasync16(d + 64 * SAS * 2, g + (size_t)64 * 1024);
        const __nv_bfloat16* gb = Bb + (size_t)(n0 + ar) * 1024 + k0 + ac;
        uint32_t db = (uint32_t)__cvta_generic_to_shared(&sB[buf][ar * SBS + ac]);
        cpasync16(db, gb);
        cpasync16(db + 64 * SBS * 2, gb + (size_t)64 * 1024);
    };

    loadTile(0, 0);
    asm volatile("cp.async.commit_group;");
    for (int kt = 0; kt < 32; ++kt) {
        if (kt + 1 < 32) {
            loadTile(kt + 1, (kt + 1) & 1);
            asm volatile("cp.async.commit_group;");
            asm volatile("cp.async.wait_group 1;");
        } else {
            asm volatile("cp.async.wait_group 0;");
        }
        __syncthreads();
        const __nv_bfloat16* cA = sA[kt & 1];
        const __nv_bfloat16* cB = sB[kt & 1];
#pragma unroll
        for (int ks = 0; ks < 32; ks += 16) {
            uint32_t af[4][4];
#pragma unroll
            for (int mi = 0; mi < 4; ++mi) {
                uint32_t addr = (uint32_t)__cvta_generic_to_shared(
                    &cA[(wm + mi * 16 + (lane & 15)) * SAS + ks + ((lane >> 4) << 3)]);
                ldsm4(af[mi], addr);
            }
            uint32_t bf[4][2];
#pragma unroll
            for (int nj = 0; nj < 2; ++nj) {
                uint32_t r[4];
                int rowb = wn + nj * 16 + (lane & 7) + (((lane >> 4) & 1) << 3);
                int kof = ks + (((lane >> 3) & 1) << 3);
                uint32_t addr = (uint32_t)__cvta_generic_to_shared(&cB[rowb * SBS + kof]);
                ldsm4(r, addr);
                bf[nj * 2][0] = r[0]; bf[nj * 2][1] = r[1];
                bf[nj * 2 + 1][0] = r[2]; bf[nj * 2 + 1][1] = r[3];
            }
#pragma unroll
            for (int mi = 0; mi < 4; ++mi)
#pragma unroll
                for (int ni = 0; ni < 4; ++ni) mma16816(c[mi][ni], af[mi], bf[ni]);
        }
        __syncthreads();
    }
#pragma unroll
    for (int mi = 0; mi < 4; ++mi) {
        int r0 = m0 + wm + mi * 16 + (lane >> 2);
#pragma unroll
        for (int ni = 0; ni < 4; ++ni) {
            int col = n0 + wn + ni * 8 + (lane & 3) * 2;
            float2 o0 = make_float2(c[mi][ni][0] * 0.03125f, c[mi][ni][1] * 0.03125f);
            float2 o1 = make_float2(c[mi][ni][2] * 0.03125f, c[mi][ni][3] * 0.03125f);
            *(float2*)&Cb[(size_t)r0 * 2048 + col] = o0;
            *(float2*)&Cb[(size_t)(r0 + 8) * 2048 + col] = o1;
        }
    }
}

// ---------------- K3: softmax in-place (probs only) ----------------
__global__ __launch_bounds__(256) void softmax_kernel(float* __restrict__ probs) {
    const size_t row = blockIdx.x;
    float* pr = probs + row * 2048;
    const int tid = threadIdx.x;
    float4 v0 = ((const float4*)pr)[tid];
    float4 v1 = ((const float4*)pr)[tid + 256];
    float m = fmaxf(fmaxf(fmaxf(v0.x, v0.y), fmaxf(v0.z, v0.w)),
                    fmaxf(fmaxf(v1.x, v1.y), fmaxf(v1.z, v1.w)));
    __shared__ float redm[8];
    __shared__ float reds[8];
#pragma unroll
    for (int off = 16; off; off >>= 1) m = fmaxf(m, __shfl_xor_sync(0xffffffffu, m, off));
    if ((tid & 31) == 0) redm[tid >> 5] = m;
    __syncthreads();
    m = redm[0];
#pragma unroll
    for (int i = 1; i < 8; ++i) m = fmaxf(m, redm[i]);
    float e[8];
    e[0] = __expf(v0.x - m); e[1] = __expf(v0.y - m); e[2] = __expf(v0.z - m); e[3] = __expf(v0.w - m);
    e[4] = __expf(v1.x - m); e[5] = __expf(v1.y - m); e[6] = __expf(v1.z - m); e[7] = __expf(v1.w - m);
    float s = 0.f;
#pragma unroll
    for (int i = 0; i < 8; ++i) s += e[i];
#pragma unroll
    for (int off = 16; off; off >>= 1) s += __shfl_xor_sync(0xffffffffu, s, off);
    __syncthreads();
    if ((tid & 31) == 0) reds[tid >> 5] = s;
    __syncthreads();
    s = 0.f;
#pragma unroll
    for (int i = 0; i < 8; ++i) s += reds[i];
    float inv = 1.f / s;
    ((float4*)pr)[tid] = make_float4(e[0] * inv, e[1] * inv, e[2] * inv, e[3] * inv);
    ((float4*)pr)[tid + 256] = make_float4(e[4] * inv, e[5] * inv, e[6] * inv, e[7] * inv);
}

// ---------------- K4: PV GEMM, A = probs fp32 converted inline to d=p-1/2048 ----------------
__global__ __launch_bounds__(256) void pv_kernel(const float* __restrict__ probs,
                                                 const __nv_bfloat16* __restrict__ V,
                                                 float* __restrict__ C,
                                                 const float* __restrict__ bias) {
    constexpr int SFS = 36;  // fp32 A staging stride
    constexpr int SAS = 40;  // bf16 A stride
    constexpr int SBS = 136;
    __shared__ __align__(16) float sAF[128 * SFS];
    __shared__ __align__(16) __nv_bfloat16 sAb[128 * SAS];
    __shared__ __align__(16) __nv_bfloat16 sB[2][32 * SBS];
    const int bz = blockIdx.z;
    const int m0 = blockIdx.y * 128, n0 = blockIdx.x * 128;
    const float* Ab = probs + (size_t)bz * 2048 * 2048;
    const __nv_bfloat16* Bb = V + (size_t)bz * 2048 * 1024;
    float* Cb = C + (size_t)bz * 2048 * 1024;
    const int tid = threadIdx.x, lane = tid & 31, warp = tid >> 5;
    const int wm = (warp >> 2) * 64, wn = (warp & 3) * 32;

    float c[4][4][4];
#pragma unroll
    for (int i = 0; i < 4; ++i)
#pragma unroll
        for (int j = 0; j < 4; ++j)
#pragma unroll
            for (int q = 0; q < 4; ++q) c[i][j][q] = 0.f;

    auto loadA = [&](int kt) {
#pragma unroll
        for (int i = 0; i < 4; ++i) {
            int idx = tid + 256 * i;
            int r = idx >> 3, ch = idx & 7;
            cpasync16((uint32_t)__cvta_generic_to_shared(&sAF[r * SFS + ch * 4]),
                      Ab + (size_t)(m0 + r) * 2048 + kt * 32 + ch * 4);
        }
    };
    auto loadB = [&](int kt, int buf) {
        int k0 = kt * 32;
        int br = tid >> 4, bcol = (tid & 15) * 8;
        const __nv_bfloat16* g = Bb + (size_t)(k0 + br) * 1024 + n0 + bcol;
        uint32_t d = (uint32_t)__cvta_generic_to_shared(&sB[buf][br * SBS + bcol]);
        cpasync16(d, g);
        cpasync16(d + 16 * SBS * 2, g + (size_t)16 * 1024);
    };

    loadA(0); loadB(0, 0);
    asm volatile("cp.async.commit_group;");
    const float cmean = 0.00048828125f;
    for (int kt = 0; kt < 64; ++kt) {
        asm volatile("cp.async.wait_group 0;");
        __syncthreads();
        // convert fp32 probs tile -> bf16 d-tile
        {
            int r = tid >> 1, base = (tid & 1) * 16;
#pragma unroll
            for (int j = 0; j < 4; ++j) {
                float4 a = *(const float4*)&sAF[r * SFS + base + 4 * j];
                __nv_bfloat162 p0 = __floats2bfloat162_rn(a.x - cmean, a.y - cmean);
                __nv_bfloat162 p1 = __floats2bfloat162_rn(a.z - cmean, a.w - cmean);
                uint2 o; o.x = *(uint32_t*)&p0; o.y = *(uint32_t*)&p1;
                *(uint2*)&sAb[r * SAS + base + 4 * j] = o;
            }
        }
        __syncthreads();
        if (kt + 1 < 64) {
            loadA(kt + 1);
            loadB(kt + 1, (kt + 1) & 1);
            asm volatile("cp.async.commit_group;");
        }
        const __nv_bfloat16* cB = sB[kt & 1];
#pragma unroll
        for (int ks = 0; ks < 32; ks += 16) {
            uint32_t af[4][4];
#pragma unroll
            for (int mi = 0; mi < 4; ++mi) {
                uint32_t addr = (uint32_t)__cvta_generic_to_shared(
                    &sAb[(wm + mi * 16 + (lane & 15)) * SAS + ks + ((lane >> 4) << 3)]);
                ldsm4(af[mi], addr);
            }
            uint32_t bf[4][2];
#pragma unroll
            for (int nj = 0; nj < 2; ++nj) {
                uint32_t r[4];
                int krow = ks + (lane & 7) + (((lane >> 3) & 1) << 3);
                int ncol = wn + nj * 16 + ((lane >> 4) << 3);
                uint32_t addr = (uint32_t)__cvta_generic_to_shared(&cB[krow * SBS + ncol]);
                ldsm4t(r, addr);
                bf[nj * 2][0] = r[0]; bf[nj * 2][1] = r[1];
                bf[nj * 2 + 1][0] = r[2]; bf[nj * 2 + 1][1] = r[3];
            }
#pragma unroll
            for (int mi = 0; mi < 4; ++mi)
#pragma unroll
                for (int ni = 0; ni < 4; ++ni) mma16816(c[mi][ni], af[mi], bf[ni]);
        }
        __syncthreads();
    }
#pragma unroll
    for (int mi = 0; mi < 4; ++mi) {
        int r0 = m0 + wm + mi * 16 + (lane >> 2);
#pragma unroll
        for (int ni = 0; ni < 4; ++ni) {
            int col = n0 + wn + ni * 8 + (lane & 3) * 2;
            float bx = bias[bz * 1024 + col] * (1.f / 2048.f);
            float by = bias[bz * 1024 + col + 1] * (1.f / 2048.f);
            float2 o0 = make_float2(c[mi][ni][0] + bx, c[mi][ni][1] + by);
            float2 o1 = make_float2(c[mi][ni][2] + bx, c[mi][ni][3] + by);
            *(float2*)&Cb[(size_t)r0 * 1024 + col] = o0;
            *(float2*)&Cb[(size_t)(r0 + 8) * 1024 + col] = o1;
        }
    }
}

// ---------------- launch ----------------
extern "C" void kernel_launch(void* const* d_in, const int* in_sizes, int n_in,
                              void* d_out, int out_size) {
    const float* x  = (const float*)d_in[0];
    const float* Wq = (const float*)d_in[1];
    const float* bq = (const float*)d_in[2];
    const float* Wk = (const float*)d_in[3];
    const float* bk = (const float*)d_in[4];
    const float* Wv = (const float*)d_in[5];
    const float* bv = (const float*)d_in[6];
    const float* Wl = (const float*)d_in[7];

    float* out = (float*)d_out;                   // [8,2048,1024]
    float* probs = out + (size_t)8 * 2048 * 1024; // [8,2048,2048]

    __nv_bfloat16 *q2b, *kb, *vb;
    float* colsumv;
    cudaGetSymbolAddress((void**)&q2b, g_q2b);
    cudaGetSymbolAddress((void**)&kb, g_kb);
    cudaGetSymbolAddress((void**)&vb, g_vb);
    cudaGetSymbolAddress((void**)&colsumv, g_colsumv);

    pack_kernel<<<(32 * 9 * 96 * 32 + 255) / 256, 256>>>(Wq, bq, Wk, Wv, Wl);
    colsumx_kernel<<<dim3(16, 8), 256>>>(x);
    colsumv_kernel<<<8, 256>>>(bv);
    convert_kernel<<<8192, 256>>>(x);
    projmma_kernel<<<dim3(32, 128), 256>>>(bk, bv);

    qk_kernel<<<dim3(16, 16, 8), 256>>>(q2b, kb, probs);
    softmax_kernel<<<16384, 256>>>(probs);
    pv_kernel<<<dim3(8, 16, 8), 256>>>(probs, vb, out, colsumv);
}